// round 11
// baseline (speedup 1.0000x reference)
#include <cuda_runtime.h>
#include <cuda_bf16.h>
#include <cstdint>

#define N_NODES 50000
#define N_EDGES 1600000
#define F_INDIM 128
#define HID     64
#define NCLS    19
#define NGRAPH  512
#define SBLK    256
#define NSBLK   ((N_NODES + SBLK - 1) / SBLK)   // 196

// ---- scratch (static device globals; no allocation) ----
__device__ int   g_ecnt[N_NODES];
__device__ int   g_off [N_NODES + 1];
__device__ int   g_cur [N_NODES];
__device__ int   g_part[NSBLK];
__device__ int2  g_edge[N_EDGES];             // packed (src, norm-bits)
__device__ float g_dinv[N_NODES];
__device__ __nv_bfloat162 g_ah[N_NODES * 32]; // bf16 gather source (64 feats/node)
__device__ float g_b   [N_NODES * HID];       // layer-1 aggregation output (fp32)
__device__ float g_pool[NGRAPH * HID];
__device__ float g_cnt [NGRAPH];

__device__ __forceinline__ void red_add_v4(float* addr, float4 v) {
    asm volatile("red.global.add.v4.f32 [%0], {%1, %2, %3, %4};"
                 :: "l"(addr), "f"(v.x), "f"(v.y), "f"(v.z), "f"(v.w)
                 : "memory");
}

// ---------------------------------------------------------------------------
__global__ void k_init() {
    int i = blockIdx.x * blockDim.x + threadIdx.x;
    if (i < N_NODES)       g_ecnt[i] = 0;
    if (i < NGRAPH * HID)  g_pool[i] = 0.f;
    if (i < NGRAPH)        g_cnt[i]  = 0.f;
}

__global__ void k_count(const int* __restrict__ ei) {
    int e = blockIdx.x * blockDim.x + threadIdx.x;
    if (e < N_EDGES) atomicAdd(&g_ecnt[ei[N_EDGES + e]], 1);
}

// ---- scan phase 1, with dinv + per-graph node count folded in -------------
__global__ void k_scan1(const int* __restrict__ batch) {
    __shared__ int sh[SBLK];
    const int t = threadIdx.x;
    const int i = blockIdx.x * SBLK + t;
    int v = (i < N_NODES) ? g_ecnt[i] : 0;
    if (i < N_NODES) {
        g_dinv[i] = rsqrtf(1.0f + (float)v);           // +1 self-loop
        atomicAdd(&g_cnt[batch[i]], 1.0f);
    }
    sh[t] = v;
    __syncthreads();
    #pragma unroll
    for (int off = 1; off < SBLK; off <<= 1) {
        int u = (t >= off) ? sh[t - off] : 0;
        __syncthreads();
        if (t >= off) sh[t] += u;
        __syncthreads();
    }
    if (i < N_NODES) g_off[i] = sh[t] - v;
    if (t == SBLK - 1) g_part[blockIdx.x] = sh[t];
}

__global__ void k_scan2() {
    __shared__ int sh[SBLK];
    const int t = threadIdx.x;
    int v = (t < NSBLK) ? g_part[t] : 0;
    sh[t] = v;
    __syncthreads();
    #pragma unroll
    for (int off = 1; off < SBLK; off <<= 1) {
        int u = (t >= off) ? sh[t - off] : 0;
        __syncthreads();
        if (t >= off) sh[t] += u;
        __syncthreads();
    }
    if (t < NSBLK) g_part[t] = sh[t] - v;
    if (t == SBLK - 1) g_off[N_NODES] = sh[t];
}

__global__ void k_scan3() {
    const int i = blockIdx.x * SBLK + threadIdx.x;
    if (i < N_NODES) {
        int o = g_off[i] + g_part[blockIdx.x];
        g_off[i] = o;
        g_cur[i] = o;
    }
}

__global__ void k_scatter(const int* __restrict__ ei) {
    int e = blockIdx.x * blockDim.x + threadIdx.x;
    if (e >= N_EDGES) return;
    int s = ei[e];
    int d = ei[N_EDGES + e];
    int pos = atomicAdd(&g_cur[d], 1);
    g_edge[pos] = make_int2(s, __float_as_int(g_dinv[s] * g_dinv[d]));
}

// ---------------------------------------------------------------------------
// Register-tiled GEMM (protected R7 shape): 256 thr, 64 nodes, 4x4 tile.
// Epilogue converts the 4-col result to 2 bf16x2 and stores 8 B to g_ah.
template <int K, bool BIAS_RELU>
__global__ void k_gemm_fused(const float* X, const float* __restrict__ W,
                             const float* __restrict__ bias) {
    constexpr int XP = K + 4;
    __shared__ float Xs[64 * XP];
    __shared__ float Ws[K * HID];
    const int tid = threadIdx.x;
    const int nb  = blockIdx.x * 64;

    for (int i = tid; i < K * HID; i += 256) Ws[i] = W[i];
    for (int i = tid; i < 64 * K; i += 256) {
        int nl = i / K, k = i % K;
        int node = nb + nl;
        float v = (node < N_NODES) ? X[node * K + k] : 0.0f;
        if (BIAS_RELU) { v += bias[k]; v = v > 0.f ? v : 0.f; }
        Xs[nl * XP + k] = v;
    }
    __syncthreads();

    const int ny0 = (tid / 16) * 4;
    const int c0  = (tid & 15) * 4;

    float4 acc[4];
    #pragma unroll
    for (int i = 0; i < 4; ++i) acc[i] = make_float4(0.f, 0.f, 0.f, 0.f);

    #pragma unroll 4
    for (int k = 0; k < K; k += 4) {
        float4 xr[4], wr[4];
        #pragma unroll
        for (int i = 0; i < 4; ++i)
            xr[i] = *reinterpret_cast<const float4*>(&Xs[(ny0 + i) * XP + k]);
        #pragma unroll
        for (int j = 0; j < 4; ++j)
            wr[j] = *reinterpret_cast<const float4*>(&Ws[(k + j) * HID + c0]);
        #pragma unroll
        for (int i = 0; i < 4; ++i) {
            const float x0 = xr[i].x, x1 = xr[i].y, x2 = xr[i].z, x3 = xr[i].w;
            acc[i].x += x0*wr[0].x + x1*wr[1].x + x2*wr[2].x + x3*wr[3].x;
            acc[i].y += x0*wr[0].y + x1*wr[1].y + x2*wr[2].y + x3*wr[3].y;
            acc[i].z += x0*wr[0].z + x1*wr[1].z + x2*wr[2].z + x3*wr[3].z;
            acc[i].w += x0*wr[0].w + x1*wr[1].w + x2*wr[2].w + x3*wr[3].w;
        }
    }

    #pragma unroll
    for (int i = 0; i < 4; ++i) {
        int node = nb + ny0 + i;
        if (node >= N_NODES) break;
        __nv_bfloat162 p0 = __float22bfloat162_rn(make_float2(acc[i].x, acc[i].y));
        __nv_bfloat162 p1 = __float22bfloat162_rn(make_float2(acc[i].z, acc[i].w));
        uint2 pk;
        pk.x = *reinterpret_cast<uint32_t*>(&p0);
        pk.y = *reinterpret_cast<uint32_t*>(&p1);
        *reinterpret_cast<uint2*>(&g_ah[node * 32 + (c0 >> 1)]) = pk;
    }
}

// ---------------------------------------------------------------------------
// CSR aggregation over bf16 rows: 8 threads per node, lane l owns features
// [8l, 8l+8) = one uint4 (4 bf16x2). Accumulate fp32 in registers.
__device__ __forceinline__ void bf16x8_fma(float* acc, uint4 raw, float n) {
    const __nv_bfloat162* p = reinterpret_cast<const __nv_bfloat162*>(&raw);
    #pragma unroll
    for (int j = 0; j < 4; ++j) {
        float2 f = __bfloat1622float2(p[j]);
        acc[2*j]   += n * f.x;
        acc[2*j+1] += n * f.y;
    }
}

template <bool POOL>
__global__ void k_agg_csr(const int* __restrict__ batch) {
    const int node = blockIdx.x * 32 + (threadIdx.x >> 3);
    const int l    = threadIdx.x & 7;          // lane within node
    if (node >= N_NODES) return;

    float acc[8] = {0,0,0,0,0,0,0,0};
    float dn = g_dinv[node]; dn *= dn;
    bf16x8_fma(acc, *reinterpret_cast<const uint4*>(&g_ah[node * 32 + l * 4]), dn);

    const int beg = g_off[node];
    const int end = g_off[node + 1];
    int e = beg;
    for (; e + 2 <= end; e += 2) {
        int2 e0 = g_edge[e], e1 = g_edge[e + 1];
        uint4 r0 = *reinterpret_cast<const uint4*>(&g_ah[e0.x * 32 + l * 4]);
        uint4 r1 = *reinterpret_cast<const uint4*>(&g_ah[e1.x * 32 + l * 4]);
        bf16x8_fma(acc, r0, __int_as_float(e0.y));
        bf16x8_fma(acc, r1, __int_as_float(e1.y));
    }
    if (e < end) {
        int2 e0 = g_edge[e];
        uint4 r0 = *reinterpret_cast<const uint4*>(&g_ah[e0.x * 32 + l * 4]);
        bf16x8_fma(acc, r0, __int_as_float(e0.y));
    }

    float4 lo = make_float4(acc[0], acc[1], acc[2], acc[3]);
    float4 hi = make_float4(acc[4], acc[5], acc[6], acc[7]);
    if (POOL) {
        int g = batch[node];
        red_add_v4(&g_pool[g * HID + l * 8],     lo);
        red_add_v4(&g_pool[g * HID + l * 8 + 4], hi);
    } else {
        *reinterpret_cast<float4*>(&g_b[node * HID + l * 8])     = lo;
        *reinterpret_cast<float4*>(&g_b[node * HID + l * 8 + 4]) = hi;
    }
}

// Warp per graph: out[g, c] = (mean(pool) + b2) @ W_out + b_out
__global__ void k_final(const float* __restrict__ b2,
                        const float* __restrict__ Wout,
                        const float* __restrict__ bout,
                        float* __restrict__ out) {
    int gt   = blockIdx.x * blockDim.x + threadIdx.x;
    int g    = gt >> 5;
    int lane = gt & 31;
    if (g >= NGRAPH || lane >= NCLS) return;
    float cnt = g_cnt[g];
    float inv = cnt > 0.f ? 1.0f / cnt : 0.0f;
    float has = cnt > 0.f ? 1.0f : 0.0f;
    float acc = bout[lane];
    #pragma unroll
    for (int h = 0; h < HID; ++h) {
        float ph = g_pool[g * HID + h] * inv + has * b2[h];
        acc += ph * Wout[h * NCLS + lane];
    }
    out[g * NCLS + lane] = acc;
}

// ---------------------------------------------------------------------------
extern "C" void kernel_launch(void* const* d_in, const int* in_sizes, int n_in,
                              void* d_out, int out_size) {
    const float* x    = (const float*)d_in[0];
    const int*   ei   = (const int*)  d_in[1];   // int32 (JAX x64 disabled)
    const int*   bat  = (const int*)  d_in[2];
    const float* W1   = (const float*)d_in[3];
    const float* b1   = (const float*)d_in[4];
    const float* W2   = (const float*)d_in[5];
    const float* b2   = (const float*)d_in[6];
    const float* Wout = (const float*)d_in[7];
    const float* bout = (const float*)d_in[8];
    float* out = (float*)d_out;

    float* pb;  cudaGetSymbolAddress((void**)&pb, g_b);

    // Side stream + fork/join events: created lazily on the FIRST call, which
    // is the uncaptured correctness run (no creation during graph capture).
    static cudaStream_t sB = nullptr;
    static cudaEvent_t evRoot = nullptr, evGemm = nullptr;
    if (sB == nullptr) {
        cudaStreamCreateWithFlags(&sB, cudaStreamNonBlocking);
        cudaEventCreateWithFlags(&evRoot, cudaEventDisableTiming);
        cudaEventCreateWithFlags(&evGemm, cudaEventDisableTiming);
    }

    const int TB = 256;
    const int initN  = (N_NODES > NGRAPH * HID) ? N_NODES : NGRAPH * HID;
    const int nblkI  = (initN + TB - 1) / TB;
    const int nblkE  = (N_EDGES + TB - 1) / TB;
    const int nblkG  = (N_NODES + 63) / 64;
    const int nblkAg = (N_NODES + 31) / 32;

    // Fork: gemm1 (x,W1 only) runs on sB concurrently with the CSR build.
    cudaEventRecord(evRoot, 0);
    cudaStreamWaitEvent(sB, evRoot, 0);
    k_gemm_fused<F_INDIM, false><<<nblkG, TB, 0, sB>>>(x, W1, nullptr);
    cudaEventRecord(evGemm, sB);

    // CSR build on the main (capture) stream.
    k_init   <<<nblkI, TB>>>();
    k_count  <<<nblkE, TB>>>(ei);
    k_scan1  <<<NSBLK, SBLK>>>(bat);     // + dinv + per-graph counts
    k_scan2  <<<1, SBLK>>>();
    k_scan3  <<<NSBLK, SBLK>>>();
    k_scatter<<<nblkE, TB>>>(ei);

    // Join: agg1 needs both gemm1 output and the CSR.
    cudaStreamWaitEvent(0, evGemm, 0);
    k_agg_csr<false><<<nblkAg, TB>>>(bat);

    // layer 2 (relu + b1 fused into gemm input; pool fused into agg)
    k_gemm_fused<HID, true><<<nblkG, TB>>>(pb, W2, b1);
    k_agg_csr<true><<<nblkAg, TB>>>(bat);

    // linear head (b2 folded in)
    k_final<<<(NGRAPH * 32 + TB - 1) / TB, TB>>>(b2, Wout, bout, out);
}

// round 12
// speedup vs baseline: 1.3138x; 1.3138x over previous
#include <cuda_runtime.h>
#include <cstdint>

#define N_NODES 50000
#define N_EDGES 1600000
#define F_INDIM 128
#define HID     64
#define NCLS    19
#define NGRAPH  512
#define SBLK    256
#define NSBLK   ((N_NODES + SBLK - 1) / SBLK)   // 196

// ---- scratch (static device globals; no allocation) ----
__device__ int   g_ecnt[N_NODES];
__device__ int   g_off [N_NODES + 1];
__device__ int   g_cur [N_NODES];
__device__ int   g_part[NSBLK];
__device__ int2  g_edge[N_EDGES];         // packed (src, __float_as_int(norm))
__device__ float g_dinv[N_NODES];
__device__ float g_a   [N_NODES * HID];   // gemm output / gather source
__device__ float g_b   [N_NODES * HID];   // layer-1 aggregation output
__device__ float g_pool[NGRAPH * HID];
__device__ float g_cnt [NGRAPH];

__device__ __forceinline__ void red_add_v4(float* addr, float4 v) {
    asm volatile("red.global.add.v4.f32 [%0], {%1, %2, %3, %4};"
                 :: "l"(addr), "f"(v.x), "f"(v.y), "f"(v.z), "f"(v.w)
                 : "memory");
}

// ---------------------------------------------------------------------------
__global__ void k_init() {
    int i = blockIdx.x * blockDim.x + threadIdx.x;
    if (i < N_NODES)       g_ecnt[i] = 0;
    if (i < NGRAPH * HID)  g_pool[i] = 0.f;
    if (i < NGRAPH)        g_cnt[i]  = 0.f;
}

__global__ void k_count(const int* __restrict__ ei) {
    int e = blockIdx.x * blockDim.x + threadIdx.x;
    if (e < N_EDGES) atomicAdd(&g_ecnt[ei[N_EDGES + e]], 1);
}

// ---- scan phase 1, with dinv + per-graph node count folded in -------------
__global__ void k_scan1(const int* __restrict__ batch) {
    __shared__ int sh[SBLK];
    const int t = threadIdx.x;
    const int i = blockIdx.x * SBLK + t;
    int v = (i < N_NODES) ? g_ecnt[i] : 0;
    if (i < N_NODES) {
        g_dinv[i] = rsqrtf(1.0f + (float)v);           // +1 self-loop
        atomicAdd(&g_cnt[batch[i]], 1.0f);
    }
    sh[t] = v;
    __syncthreads();
    #pragma unroll
    for (int off = 1; off < SBLK; off <<= 1) {
        int u = (t >= off) ? sh[t - off] : 0;
        __syncthreads();
        if (t >= off) sh[t] += u;
        __syncthreads();
    }
    if (i < N_NODES) g_off[i] = sh[t] - v;
    if (t == SBLK - 1) g_part[blockIdx.x] = sh[t];
}

__global__ void k_scan2() {
    __shared__ int sh[SBLK];
    const int t = threadIdx.x;
    int v = (t < NSBLK) ? g_part[t] : 0;
    sh[t] = v;
    __syncthreads();
    #pragma unroll
    for (int off = 1; off < SBLK; off <<= 1) {
        int u = (t >= off) ? sh[t - off] : 0;
        __syncthreads();
        if (t >= off) sh[t] += u;
        __syncthreads();
    }
    if (t < NSBLK) g_part[t] = sh[t] - v;
    if (t == SBLK - 1) g_off[N_NODES] = sh[t];
}

__global__ void k_scan3() {
    const int i = blockIdx.x * SBLK + threadIdx.x;
    if (i < N_NODES) {
        int o = g_off[i] + g_part[blockIdx.x];
        g_off[i] = o;
        g_cur[i] = o;
    }
}

__global__ void k_scatter(const int* __restrict__ ei) {
    int e = blockIdx.x * blockDim.x + threadIdx.x;
    if (e >= N_EDGES) return;
    int s = ei[e];
    int d = ei[N_EDGES + e];
    int pos = atomicAdd(&g_cur[d], 1);
    g_edge[pos] = make_int2(s, __float_as_int(g_dinv[s] * g_dinv[d]));
}

// ---------------------------------------------------------------------------
// Register-tiled GEMM (protected R7 shape): 256 thr, 64 nodes, 4x4 tile.
template <int K, bool BIAS_RELU>
__global__ void k_gemm_fused(const float* X, const float* __restrict__ W,
                             const float* __restrict__ bias, float* out) {
    constexpr int XP = K + 4;
    __shared__ float Xs[64 * XP];
    __shared__ float Ws[K * HID];
    const int tid = threadIdx.x;
    const int nb  = blockIdx.x * 64;

    for (int i = tid; i < K * HID; i += 256) Ws[i] = W[i];
    for (int i = tid; i < 64 * K; i += 256) {
        int nl = i / K, k = i % K;
        int node = nb + nl;
        float v = (node < N_NODES) ? X[node * K + k] : 0.0f;
        if (BIAS_RELU) { v += bias[k]; v = v > 0.f ? v : 0.f; }
        Xs[nl * XP + k] = v;
    }
    __syncthreads();

    const int ny0 = (tid / 16) * 4;
    const int c0  = (tid & 15) * 4;

    float4 acc[4];
    #pragma unroll
    for (int i = 0; i < 4; ++i) acc[i] = make_float4(0.f, 0.f, 0.f, 0.f);

    #pragma unroll 4
    for (int k = 0; k < K; k += 4) {
        float4 xr[4], wr[4];
        #pragma unroll
        for (int i = 0; i < 4; ++i)
            xr[i] = *reinterpret_cast<const float4*>(&Xs[(ny0 + i) * XP + k]);
        #pragma unroll
        for (int j = 0; j < 4; ++j)
            wr[j] = *reinterpret_cast<const float4*>(&Ws[(k + j) * HID + c0]);
        #pragma unroll
        for (int i = 0; i < 4; ++i) {
            const float x0 = xr[i].x, x1 = xr[i].y, x2 = xr[i].z, x3 = xr[i].w;
            acc[i].x += x0*wr[0].x + x1*wr[1].x + x2*wr[2].x + x3*wr[3].x;
            acc[i].y += x0*wr[0].y + x1*wr[1].y + x2*wr[2].y + x3*wr[3].y;
            acc[i].z += x0*wr[0].z + x1*wr[1].z + x2*wr[2].z + x3*wr[3].z;
            acc[i].w += x0*wr[0].w + x1*wr[1].w + x2*wr[2].w + x3*wr[3].w;
        }
    }

    #pragma unroll
    for (int i = 0; i < 4; ++i) {
        int node = nb + ny0 + i;
        if (node >= N_NODES) break;
        *reinterpret_cast<float4*>(&out[node * HID + c0]) = acc[i];
    }
}

// ---------------------------------------------------------------------------
// CSR aggregation, float4 lanes: 16 threads per node. 4-deep edge unroll:
// 4 independent int2 + 4 independent float4 gathers in flight (latency-bound).
template <bool POOL>
__global__ void k_agg_csr(const int* __restrict__ batch) {
    const int node = blockIdx.x * 16 + (threadIdx.x >> 4);
    const int c0   = (threadIdx.x & 15) * 4;
    if (node >= N_NODES) return;

    float dn = g_dinv[node]; dn *= dn;
    float4 acc = *reinterpret_cast<const float4*>(&g_a[node * HID + c0]);
    acc.x *= dn; acc.y *= dn; acc.z *= dn; acc.w *= dn;

    const int beg = g_off[node];
    const int end = g_off[node + 1];
    int e = beg;
    for (; e + 4 <= end; e += 4) {
        int2 e0 = g_edge[e],     e1 = g_edge[e + 1];
        int2 e2 = g_edge[e + 2], e3 = g_edge[e + 3];
        float4 v0 = *reinterpret_cast<const float4*>(&g_a[e0.x * HID + c0]);
        float4 v1 = *reinterpret_cast<const float4*>(&g_a[e1.x * HID + c0]);
        float4 v2 = *reinterpret_cast<const float4*>(&g_a[e2.x * HID + c0]);
        float4 v3 = *reinterpret_cast<const float4*>(&g_a[e3.x * HID + c0]);
        float n0 = __int_as_float(e0.y), n1 = __int_as_float(e1.y);
        float n2 = __int_as_float(e2.y), n3 = __int_as_float(e3.y);
        acc.x += n0*v0.x + n1*v1.x + n2*v2.x + n3*v3.x;
        acc.y += n0*v0.y + n1*v1.y + n2*v2.y + n3*v3.y;
        acc.z += n0*v0.z + n1*v1.z + n2*v2.z + n3*v3.z;
        acc.w += n0*v0.w + n1*v1.w + n2*v2.w + n3*v3.w;
    }
    for (; e < end; ++e) {
        int2 e0 = g_edge[e];
        float n0 = __int_as_float(e0.y);
        float4 v0 = *reinterpret_cast<const float4*>(&g_a[e0.x * HID + c0]);
        acc.x += n0 * v0.x; acc.y += n0 * v0.y;
        acc.z += n0 * v0.z; acc.w += n0 * v0.w;
    }

    if (POOL) {
        int g = batch[node];
        red_add_v4(&g_pool[g * HID + c0], acc);
    } else {
        *reinterpret_cast<float4*>(&g_b[node * HID + c0]) = acc;
    }
}

// Warp per graph: out[g, c] = (mean(pool) + b2) @ W_out + b_out
__global__ void k_final(const float* __restrict__ b2,
                        const float* __restrict__ Wout,
                        const float* __restrict__ bout,
                        float* __restrict__ out) {
    int gt   = blockIdx.x * blockDim.x + threadIdx.x;
    int g    = gt >> 5;
    int lane = gt & 31;
    if (g >= NGRAPH || lane >= NCLS) return;
    float cnt = g_cnt[g];
    float inv = cnt > 0.f ? 1.0f / cnt : 0.0f;
    float has = cnt > 0.f ? 1.0f : 0.0f;
    float acc = bout[lane];
    #pragma unroll
    for (int h = 0; h < HID; ++h) {
        float ph = g_pool[g * HID + h] * inv + has * b2[h];
        acc += ph * Wout[h * NCLS + lane];
    }
    out[g * NCLS + lane] = acc;
}

// ---------------------------------------------------------------------------
extern "C" void kernel_launch(void* const* d_in, const int* in_sizes, int n_in,
                              void* d_out, int out_size) {
    const float* x    = (const float*)d_in[0];
    const int*   ei   = (const int*)  d_in[1];   // int32 (JAX x64 disabled)
    const int*   bat  = (const int*)  d_in[2];
    const float* W1   = (const float*)d_in[3];
    const float* b1   = (const float*)d_in[4];
    const float* W2   = (const float*)d_in[5];
    const float* b2   = (const float*)d_in[6];
    const float* Wout = (const float*)d_in[7];
    const float* bout = (const float*)d_in[8];
    float* out = (float*)d_out;

    float* pa;  cudaGetSymbolAddress((void**)&pa, g_a);
    float* pb;  cudaGetSymbolAddress((void**)&pb, g_b);

    // Side stream + fork/join events: created lazily on the FIRST call, which
    // is the uncaptured correctness run (no creation during graph capture).
    static cudaStream_t sB = nullptr;
    static cudaEvent_t evRoot = nullptr, evGemm = nullptr;
    if (sB == nullptr) {
        cudaStreamCreateWithFlags(&sB, cudaStreamNonBlocking);
        cudaEventCreateWithFlags(&evRoot, cudaEventDisableTiming);
        cudaEventCreateWithFlags(&evGemm, cudaEventDisableTiming);
    }

    const int TB = 256;
    const int initN  = (N_NODES > NGRAPH * HID) ? N_NODES : NGRAPH * HID;
    const int nblkI  = (initN + TB - 1) / TB;
    const int nblkE  = (N_EDGES + TB - 1) / TB;
    const int nblkG  = (N_NODES + 63) / 64;
    const int nblkAg = (N_NODES + 15) / 16;

    // Fork: gemm1 (x,W1 only) runs on sB concurrently with the CSR build.
    cudaEventRecord(evRoot, 0);
    cudaStreamWaitEvent(sB, evRoot, 0);
    k_gemm_fused<F_INDIM, false><<<nblkG, TB, 0, sB>>>(x, W1, nullptr, pa);
    cudaEventRecord(evGemm, sB);

    // CSR build on the main (capture) stream.
    k_init   <<<nblkI, TB>>>();
    k_count  <<<nblkE, TB>>>(ei);
    k_scan1  <<<NSBLK, SBLK>>>(bat);     // + dinv + per-graph counts
    k_scan2  <<<1, SBLK>>>();
    k_scan3  <<<NSBLK, SBLK>>>();
    k_scatter<<<nblkE, TB>>>(ei);

    // Join: agg1 needs both gemm1 output and the CSR.
    cudaStreamWaitEvent(0, evGemm, 0);
    k_agg_csr<false><<<nblkAg, TB>>>(bat);

    // layer 2 (relu + b1 fused into gemm input; pool fused into agg)
    k_gemm_fused<HID, true><<<nblkG, TB>>>(pb, W2, b1, pa);
    k_agg_csr<true><<<nblkAg, TB>>>(bat);

    // linear head (b2 folded in)
    k_final<<<(NGRAPH * 32 + TB - 1) / TB, TB>>>(b2, Wout, bout, out);
}

// round 13
// speedup vs baseline: 1.5276x; 1.1627x over previous
#include <cuda_runtime.h>
#include <cstdint>

#define N_NODES 50000
#define N_EDGES 1600000
#define F_INDIM 128
#define HID     64
#define NCLS    19
#define NGRAPH  512
#define SBLK    256
#define NSBLK   ((N_NODES + SBLK - 1) / SBLK)   // 196

// ---- scratch (static device globals; no allocation) ----
__device__ int   g_ecnt[N_NODES];
__device__ int   g_off [N_NODES + 1];
__device__ int   g_cur [N_NODES];
__device__ int   g_part[NSBLK];
__device__ int2  g_edge[N_EDGES];         // packed (src, __float_as_int(norm))
__device__ float g_dinv[N_NODES];
__device__ float g_a   [N_NODES * HID];   // gemm1 output
__device__ float g_b   [N_NODES * HID];   // h1 = relu(agg1 + b1)
__device__ float g_pool[NGRAPH * HID];
__device__ float g_cnt [NGRAPH];
__device__ float g_M   [HID * NCLS];      // W2 @ Wout
__device__ float g_bv  [NCLS];            // b2 @ Wout

__device__ __forceinline__ void red_add_v4(float* addr, float4 v) {
    asm volatile("red.global.add.v4.f32 [%0], {%1, %2, %3, %4};"
                 :: "l"(addr), "f"(v.x), "f"(v.y), "f"(v.z), "f"(v.w)
                 : "memory");
}

// ---------------------------------------------------------------------------
__global__ void k_init() {
    int i = blockIdx.x * blockDim.x + threadIdx.x;
    if (i < N_NODES)       g_ecnt[i] = 0;
    if (i < NGRAPH * HID)  g_pool[i] = 0.f;
    if (i < NGRAPH)        g_cnt[i]  = 0.f;
}

__global__ void k_count(const int* __restrict__ ei) {
    int e = blockIdx.x * blockDim.x + threadIdx.x;
    if (e < N_EDGES) atomicAdd(&g_ecnt[ei[N_EDGES + e]], 1);
}

// ---- scan phase 1, with dinv + per-graph node count folded in -------------
__global__ void k_scan1(const int* __restrict__ batch) {
    __shared__ int sh[SBLK];
    const int t = threadIdx.x;
    const int i = blockIdx.x * SBLK + t;
    int v = (i < N_NODES) ? g_ecnt[i] : 0;
    if (i < N_NODES) {
        g_dinv[i] = rsqrtf(1.0f + (float)v);           // +1 self-loop
        atomicAdd(&g_cnt[batch[i]], 1.0f);
    }
    sh[t] = v;
    __syncthreads();
    #pragma unroll
    for (int off = 1; off < SBLK; off <<= 1) {
        int u = (t >= off) ? sh[t - off] : 0;
        __syncthreads();
        if (t >= off) sh[t] += u;
        __syncthreads();
    }
    if (i < N_NODES) g_off[i] = sh[t] - v;
    if (t == SBLK - 1) g_part[blockIdx.x] = sh[t];
}

__global__ void k_scan2() {
    __shared__ int sh[SBLK];
    const int t = threadIdx.x;
    int v = (t < NSBLK) ? g_part[t] : 0;
    sh[t] = v;
    __syncthreads();
    #pragma unroll
    for (int off = 1; off < SBLK; off <<= 1) {
        int u = (t >= off) ? sh[t - off] : 0;
        __syncthreads();
        if (t >= off) sh[t] += u;
        __syncthreads();
    }
    if (t < NSBLK) g_part[t] = sh[t] - v;
    if (t == SBLK - 1) g_off[N_NODES] = sh[t];
}

__global__ void k_scan3() {
    const int i = blockIdx.x * SBLK + threadIdx.x;
    if (i < N_NODES) {
        int o = g_off[i] + g_part[blockIdx.x];
        g_off[i] = o;
        g_cur[i] = o;
    }
}

__global__ void k_scatter(const int* __restrict__ ei) {
    int e = blockIdx.x * blockDim.x + threadIdx.x;
    if (e >= N_EDGES) return;
    int s = ei[e];
    int d = ei[N_EDGES + e];
    int pos = atomicAdd(&g_cur[d], 1);
    g_edge[pos] = make_int2(s, __float_as_int(g_dinv[s] * g_dinv[d]));
}

// ---------------------------------------------------------------------------
// Tiny precompute: M = W2 @ Wout [64,19], bv = b2 @ Wout [19]. One block.
__global__ void k_prep(const float* __restrict__ W2, const float* __restrict__ b2,
                       const float* __restrict__ Wout) {
    int idx = threadIdx.x;                              // 256 threads
    for (int i = idx; i < HID * NCLS; i += 256) {
        int k = i / NCLS, c = i % NCLS;
        float s = 0.f;
        #pragma unroll
        for (int h = 0; h < HID; ++h) s += W2[k * HID + h] * Wout[h * NCLS + c];
        g_M[i] = s;
    }
    if (idx < NCLS) {
        float s = 0.f;
        #pragma unroll
        for (int h = 0; h < HID; ++h) s += b2[h] * Wout[h * NCLS + idx];
        g_bv[idx] = s;
    }
}

// ---------------------------------------------------------------------------
// Register-tiled GEMM (protected R7 shape): 256 thr, 64 nodes, 4x4 tile.
// Only used for layer 1 now: g_a = x @ W1.
template <int K>
__global__ void k_gemm(const float* __restrict__ X, const float* __restrict__ W,
                       float* __restrict__ out) {
    constexpr int XP = K + 4;
    __shared__ float Xs[64 * XP];
    __shared__ float Ws[K * HID];
    const int tid = threadIdx.x;
    const int nb  = blockIdx.x * 64;

    for (int i = tid; i < K * HID; i += 256) Ws[i] = W[i];
    for (int i = tid; i < 64 * K; i += 256) {
        int nl = i / K, k = i % K;
        int node = nb + nl;
        Xs[nl * XP + k] = (node < N_NODES) ? X[node * K + k] : 0.0f;
    }
    __syncthreads();

    const int ny0 = (tid / 16) * 4;
    const int c0  = (tid & 15) * 4;

    float4 acc[4];
    #pragma unroll
    for (int i = 0; i < 4; ++i) acc[i] = make_float4(0.f, 0.f, 0.f, 0.f);

    #pragma unroll 4
    for (int k = 0; k < K; k += 4) {
        float4 xr[4], wr[4];
        #pragma unroll
        for (int i = 0; i < 4; ++i)
            xr[i] = *reinterpret_cast<const float4*>(&Xs[(ny0 + i) * XP + k]);
        #pragma unroll
        for (int j = 0; j < 4; ++j)
            wr[j] = *reinterpret_cast<const float4*>(&Ws[(k + j) * HID + c0]);
        #pragma unroll
        for (int i = 0; i < 4; ++i) {
            const float x0 = xr[i].x, x1 = xr[i].y, x2 = xr[i].z, x3 = xr[i].w;
            acc[i].x += x0*wr[0].x + x1*wr[1].x + x2*wr[2].x + x3*wr[3].x;
            acc[i].y += x0*wr[0].y + x1*wr[1].y + x2*wr[2].y + x3*wr[3].y;
            acc[i].z += x0*wr[0].z + x1*wr[1].z + x2*wr[2].z + x3*wr[3].z;
            acc[i].w += x0*wr[0].w + x1*wr[1].w + x2*wr[2].w + x3*wr[3].w;
        }
    }

    #pragma unroll
    for (int i = 0; i < 4; ++i) {
        int node = nb + ny0 + i;
        if (node >= N_NODES) break;
        *reinterpret_cast<float4*>(&out[node * HID + c0]) = acc[i];
    }
}

// ---------------------------------------------------------------------------
// CSR aggregation, float4 lanes: 16 threads per node, 4-deep edge unroll.
// Layer 1 (POOL=false): src = g_a, epilogue writes g_b = relu(acc + b1).
// Layer 2 (POOL=true):  src = g_b, epilogue red.v4 into g_pool (mean-pool sums).
template <bool POOL>
__global__ void k_agg_csr(const int* __restrict__ batch,
                          const float* __restrict__ bias) {
    const int node = blockIdx.x * 16 + (threadIdx.x >> 4);
    const int c0   = (threadIdx.x & 15) * 4;
    if (node >= N_NODES) return;

    const float* __restrict__ src = POOL ? g_b : g_a;

    float dn = g_dinv[node]; dn *= dn;
    float4 acc = *reinterpret_cast<const float4*>(&src[node * HID + c0]);
    acc.x *= dn; acc.y *= dn; acc.z *= dn; acc.w *= dn;

    const int beg = g_off[node];
    const int end = g_off[node + 1];
    int e = beg;
    for (; e + 4 <= end; e += 4) {
        int2 e0 = g_edge[e],     e1 = g_edge[e + 1];
        int2 e2 = g_edge[e + 2], e3 = g_edge[e + 3];
        float4 v0 = *reinterpret_cast<const float4*>(&src[e0.x * HID + c0]);
        float4 v1 = *reinterpret_cast<const float4*>(&src[e1.x * HID + c0]);
        float4 v2 = *reinterpret_cast<const float4*>(&src[e2.x * HID + c0]);
        float4 v3 = *reinterpret_cast<const float4*>(&src[e3.x * HID + c0]);
        float n0 = __int_as_float(e0.y), n1 = __int_as_float(e1.y);
        float n2 = __int_as_float(e2.y), n3 = __int_as_float(e3.y);
        acc.x += n0*v0.x + n1*v1.x + n2*v2.x + n3*v3.x;
        acc.y += n0*v0.y + n1*v1.y + n2*v2.y + n3*v3.y;
        acc.z += n0*v0.z + n1*v1.z + n2*v2.z + n3*v3.z;
        acc.w += n0*v0.w + n1*v1.w + n2*v2.w + n3*v3.w;
    }
    for (; e < end; ++e) {
        int2 e0 = g_edge[e];
        float n0 = __int_as_float(e0.y);
        float4 v0 = *reinterpret_cast<const float4*>(&src[e0.x * HID + c0]);
        acc.x += n0 * v0.x; acc.y += n0 * v0.y;
        acc.z += n0 * v0.z; acc.w += n0 * v0.w;
    }

    if (POOL) {
        int g = batch[node];
        red_add_v4(&g_pool[g * HID + c0], acc);
    } else {
        float4 b = *reinterpret_cast<const float4*>(&bias[c0]);
        acc.x = fmaxf(acc.x + b.x, 0.f);
        acc.y = fmaxf(acc.y + b.y, 0.f);
        acc.z = fmaxf(acc.z + b.z, 0.f);
        acc.w = fmaxf(acc.w + b.w, 0.f);
        *reinterpret_cast<float4*>(&g_b[node * HID + c0]) = acc;
    }
}

// Warp per graph: out[g, c] = (pool[g]/cnt) @ M + has*bv + bout
__global__ void k_final(const float* __restrict__ bout,
                        float* __restrict__ out) {
    int gt   = blockIdx.x * blockDim.x + threadIdx.x;
    int g    = gt >> 5;
    int lane = gt & 31;
    if (g >= NGRAPH || lane >= NCLS) return;
    float cnt = g_cnt[g];
    float inv = cnt > 0.f ? 1.0f / cnt : 0.0f;
    float has = cnt > 0.f ? 1.0f : 0.0f;
    float acc = bout[lane] + has * g_bv[lane];
    #pragma unroll
    for (int h = 0; h < HID; ++h)
        acc += g_pool[g * HID + h] * inv * g_M[h * NCLS + lane];
    out[g * NCLS + lane] = acc;
}

// ---------------------------------------------------------------------------
extern "C" void kernel_launch(void* const* d_in, const int* in_sizes, int n_in,
                              void* d_out, int out_size) {
    const float* x    = (const float*)d_in[0];
    const int*   ei   = (const int*)  d_in[1];   // int32 (JAX x64 disabled)
    const int*   bat  = (const int*)  d_in[2];
    const float* W1   = (const float*)d_in[3];
    const float* b1   = (const float*)d_in[4];
    const float* W2   = (const float*)d_in[5];
    const float* b2   = (const float*)d_in[6];
    const float* Wout = (const float*)d_in[7];
    const float* bout = (const float*)d_in[8];
    float* out = (float*)d_out;

    float* pa;  cudaGetSymbolAddress((void**)&pa, g_a);

    // Side stream + fork/join events: created lazily on the FIRST call, which
    // is the uncaptured correctness run (no creation during graph capture).
    static cudaStream_t sB = nullptr;
    static cudaEvent_t evRoot = nullptr, evGemm = nullptr;
    if (sB == nullptr) {
        cudaStreamCreateWithFlags(&sB, cudaStreamNonBlocking);
        cudaEventCreateWithFlags(&evRoot, cudaEventDisableTiming);
        cudaEventCreateWithFlags(&evGemm, cudaEventDisableTiming);
    }

    const int TB = 256;
    const int initN  = (N_NODES > NGRAPH * HID) ? N_NODES : NGRAPH * HID;
    const int nblkI  = (initN + TB - 1) / TB;
    const int nblkE  = (N_EDGES + TB - 1) / TB;
    const int nblkG  = (N_NODES + 63) / 64;
    const int nblkAg = (N_NODES + 15) / 16;

    // Fork: gemm1 + head precompute (x,W1,W2,b2,Wout only) on sB,
    // concurrent with the CSR build.
    cudaEventRecord(evRoot, 0);
    cudaStreamWaitEvent(sB, evRoot, 0);
    k_gemm<F_INDIM><<<nblkG, TB, 0, sB>>>(x, W1, pa);
    k_prep<<<1, TB, 0, sB>>>(W2, b2, Wout);
    cudaEventRecord(evGemm, sB);

    // CSR build on the main (capture) stream.
    k_init   <<<nblkI, TB>>>();
    k_count  <<<nblkE, TB>>>(ei);
    k_scan1  <<<NSBLK, SBLK>>>(bat);     // + dinv + per-graph counts
    k_scan2  <<<1, SBLK>>>();
    k_scan3  <<<NSBLK, SBLK>>>();
    k_scatter<<<nblkE, TB>>>(ei);

    // Join: agg1 needs gemm1 output and the CSR. Epilogue applies relu(+b1).
    cudaStreamWaitEvent(0, evGemm, 0);
    k_agg_csr<false><<<nblkAg, TB>>>(bat, b1);

    // Layer-2 aggregation fused with mean pooling (gemm2 eliminated:
    // pool(S(h W2)) == pool(S h) W2, folded into the head via M = W2 Wout).
    k_agg_csr<true><<<nblkAg, TB>>>(bat, nullptr);

    // Head: out = (pool/cnt) @ M + has*(b2 Wout) + bout
    k_final<<<(NGRAPH * 32 + TB - 1) / TB, TB>>>(bout, out);
}

// round 14
// speedup vs baseline: 1.5600x; 1.0212x over previous
#include <cuda_runtime.h>
#include <cstdint>

#define N_NODES 50000
#define N_EDGES 1600000
#define F_INDIM 128
#define HID     64
#define NCLS    19
#define NGRAPH  512
#define SBLK    256
#define NSBLK   ((N_NODES + SBLK - 1) / SBLK)   // 196

// ---- scratch (static device globals; no allocation) ----
__device__ int   g_ecnt[N_NODES];
__device__ int   g_off [N_NODES + 1];
__device__ int   g_cur [N_NODES];
__device__ int   g_part[NSBLK];
__device__ int2  g_edge[N_EDGES];         // packed (src, __float_as_int(norm))
__device__ float g_dinv[N_NODES];
__device__ float g_a   [N_NODES * HID];   // gemm1 output
__device__ float g_b   [N_NODES * HID];   // h1 = relu(agg1 + b1)
__device__ float g_pool[NGRAPH * HID];
__device__ int   g_gs  [NGRAPH];          // first node index of graph (sorted batch)
__device__ int   g_ge  [NGRAPH];          // one past last node index
__device__ float g_M   [HID * NCLS];      // W2 @ Wout
__device__ float g_bv  [NCLS];            // b2 @ Wout

__device__ __forceinline__ void red_add_v4(float* addr, float4 v) {
    asm volatile("red.global.add.v4.f32 [%0], {%1, %2, %3, %4};"
                 :: "l"(addr), "f"(v.x), "f"(v.y), "f"(v.z), "f"(v.w)
                 : "memory");
}

// ---------------------------------------------------------------------------
__global__ void k_init() {
    int i = blockIdx.x * blockDim.x + threadIdx.x;
    if (i < N_NODES)       g_ecnt[i] = 0;
    if (i < NGRAPH * HID)  g_pool[i] = 0.f;
    if (i < NGRAPH)        { g_gs[i] = 0; g_ge[i] = 0; }
}

// 4 consecutive-stride edges per thread: 4 independent REDs in flight.
__global__ void k_count(const int* __restrict__ ei) {
    const int base = blockIdx.x * 1024 + threadIdx.x;
    #pragma unroll
    for (int j = 0; j < 4; ++j) {
        int e = base + j * 256;
        if (e < N_EDGES) atomicAdd(&g_ecnt[ei[N_EDGES + e]], 1);
    }
}

// ---- scan phase 1 (+dinv; no atomics) --------------------------------------
__global__ void k_scan1() {
    __shared__ int sh[SBLK];
    const int t = threadIdx.x;
    const int i = blockIdx.x * SBLK + t;
    int v = (i < N_NODES) ? g_ecnt[i] : 0;
    if (i < N_NODES) g_dinv[i] = rsqrtf(1.0f + (float)v);   // +1 self-loop
    sh[t] = v;
    __syncthreads();
    #pragma unroll
    for (int off = 1; off < SBLK; off <<= 1) {
        int u = (t >= off) ? sh[t - off] : 0;
        __syncthreads();
        if (t >= off) sh[t] += u;
        __syncthreads();
    }
    if (i < N_NODES) g_off[i] = sh[t] - v;
    if (t == SBLK - 1) g_part[blockIdx.x] = sh[t];
}

__global__ void k_scan2() {
    __shared__ int sh[SBLK];
    const int t = threadIdx.x;
    int v = (t < NSBLK) ? g_part[t] : 0;
    sh[t] = v;
    __syncthreads();
    #pragma unroll
    for (int off = 1; off < SBLK; off <<= 1) {
        int u = (t >= off) ? sh[t - off] : 0;
        __syncthreads();
        if (t >= off) sh[t] += u;
        __syncthreads();
    }
    if (t < NSBLK) g_part[t] = sh[t] - v;
    if (t == SBLK - 1) g_off[N_NODES] = sh[t];
}

// Phase 3 + graph segment boundaries (batch is sorted; no atomics).
__global__ void k_scan3(const int* __restrict__ batch) {
    const int i = blockIdx.x * SBLK + threadIdx.x;
    if (i < N_NODES) {
        int o = g_off[i] + g_part[blockIdx.x];
        g_off[i] = o;
        g_cur[i] = o;
        int b  = batch[i];
        int bl = (i > 0)           ? batch[i - 1] : -1;
        int br = (i < N_NODES - 1) ? batch[i + 1] : -1;
        if (b != bl) g_gs[b] = i;
        if (b != br) g_ge[b] = i + 1;
    }
}

// 4 edges per thread.
__global__ void k_scatter(const int* __restrict__ ei) {
    const int base = blockIdx.x * 1024 + threadIdx.x;
    #pragma unroll
    for (int j = 0; j < 4; ++j) {
        int e = base + j * 256;
        if (e < N_EDGES) {
            int s = ei[e];
            int d = ei[N_EDGES + e];
            int pos = atomicAdd(&g_cur[d], 1);
            g_edge[pos] = make_int2(s, __float_as_int(g_dinv[s] * g_dinv[d]));
        }
    }
}

// ---------------------------------------------------------------------------
// Tiny precompute: M = W2 @ Wout [64,19], bv = b2 @ Wout [19]. One block.
__global__ void k_prep(const float* __restrict__ W2, const float* __restrict__ b2,
                       const float* __restrict__ Wout) {
    int idx = threadIdx.x;                              // 256 threads
    for (int i = idx; i < HID * NCLS; i += 256) {
        int k = i / NCLS, c = i % NCLS;
        float s = 0.f;
        #pragma unroll
        for (int h = 0; h < HID; ++h) s += W2[k * HID + h] * Wout[h * NCLS + c];
        g_M[i] = s;
    }
    if (idx < NCLS) {
        float s = 0.f;
        #pragma unroll
        for (int h = 0; h < HID; ++h) s += b2[h] * Wout[h * NCLS + idx];
        g_bv[idx] = s;
    }
}

// ---------------------------------------------------------------------------
// Register-tiled GEMM (protected R7 shape): 256 thr, 64 nodes, 4x4 tile.
template <int K>
__global__ void k_gemm(const float* __restrict__ X, const float* __restrict__ W,
                       float* __restrict__ out) {
    constexpr int XP = K + 4;
    __shared__ float Xs[64 * XP];
    __shared__ float Ws[K * HID];
    const int tid = threadIdx.x;
    const int nb  = blockIdx.x * 64;

    for (int i = tid; i < K * HID; i += 256) Ws[i] = W[i];
    for (int i = tid; i < 64 * K; i += 256) {
        int nl = i / K, k = i % K;
        int node = nb + nl;
        Xs[nl * XP + k] = (node < N_NODES) ? X[node * K + k] : 0.0f;
    }
    __syncthreads();

    const int ny0 = (tid / 16) * 4;
    const int c0  = (tid & 15) * 4;

    float4 acc[4];
    #pragma unroll
    for (int i = 0; i < 4; ++i) acc[i] = make_float4(0.f, 0.f, 0.f, 0.f);

    #pragma unroll 4
    for (int k = 0; k < K; k += 4) {
        float4 xr[4], wr[4];
        #pragma unroll
        for (int i = 0; i < 4; ++i)
            xr[i] = *reinterpret_cast<const float4*>(&Xs[(ny0 + i) * XP + k]);
        #pragma unroll
        for (int j = 0; j < 4; ++j)
            wr[j] = *reinterpret_cast<const float4*>(&Ws[(k + j) * HID + c0]);
        #pragma unroll
        for (int i = 0; i < 4; ++i) {
            const float x0 = xr[i].x, x1 = xr[i].y, x2 = xr[i].z, x3 = xr[i].w;
            acc[i].x += x0*wr[0].x + x1*wr[1].x + x2*wr[2].x + x3*wr[3].x;
            acc[i].y += x0*wr[0].y + x1*wr[1].y + x2*wr[2].y + x3*wr[3].y;
            acc[i].z += x0*wr[0].z + x1*wr[1].z + x2*wr[2].z + x3*wr[3].z;
            acc[i].w += x0*wr[0].w + x1*wr[1].w + x2*wr[2].w + x3*wr[3].w;
        }
    }

    #pragma unroll
    for (int i = 0; i < 4; ++i) {
        int node = nb + ny0 + i;
        if (node >= N_NODES) break;
        *reinterpret_cast<float4*>(&out[node * HID + c0]) = acc[i];
    }
}

// ---------------------------------------------------------------------------
// CSR aggregation, float4 lanes: 16 threads per node, 4-deep edge unroll.
// Layer 1 (POOL=false): src = g_a, epilogue writes g_b = relu(acc + b1).
// Layer 2 (POOL=true):  src = g_b, epilogue red.v4 into g_pool.
template <bool POOL>
__global__ void k_agg_csr(const int* __restrict__ batch,
                          const float* __restrict__ bias) {
    const int node = blockIdx.x * 16 + (threadIdx.x >> 4);
    const int c0   = (threadIdx.x & 15) * 4;
    if (node >= N_NODES) return;

    const float* __restrict__ src = POOL ? g_b : g_a;

    float dn = g_dinv[node]; dn *= dn;
    float4 acc = *reinterpret_cast<const float4*>(&src[node * HID + c0]);
    acc.x *= dn; acc.y *= dn; acc.z *= dn; acc.w *= dn;

    const int beg = g_off[node];
    const int end = g_off[node + 1];
    int e = beg;
    for (; e + 4 <= end; e += 4) {
        int2 e0 = g_edge[e],     e1 = g_edge[e + 1];
        int2 e2 = g_edge[e + 2], e3 = g_edge[e + 3];
        float4 v0 = *reinterpret_cast<const float4*>(&src[e0.x * HID + c0]);
        float4 v1 = *reinterpret_cast<const float4*>(&src[e1.x * HID + c0]);
        float4 v2 = *reinterpret_cast<const float4*>(&src[e2.x * HID + c0]);
        float4 v3 = *reinterpret_cast<const float4*>(&src[e3.x * HID + c0]);
        float n0 = __int_as_float(e0.y), n1 = __int_as_float(e1.y);
        float n2 = __int_as_float(e2.y), n3 = __int_as_float(e3.y);
        acc.x += n0*v0.x + n1*v1.x + n2*v2.x + n3*v3.x;
        acc.y += n0*v0.y + n1*v1.y + n2*v2.y + n3*v3.y;
        acc.z += n0*v0.z + n1*v1.z + n2*v2.z + n3*v3.z;
        acc.w += n0*v0.w + n1*v1.w + n2*v2.w + n3*v3.w;
    }
    for (; e < end; ++e) {
        int2 e0 = g_edge[e];
        float n0 = __int_as_float(e0.y);
        float4 v0 = *reinterpret_cast<const float4*>(&src[e0.x * HID + c0]);
        acc.x += n0 * v0.x; acc.y += n0 * v0.y;
        acc.z += n0 * v0.z; acc.w += n0 * v0.w;
    }

    if (POOL) {
        int g = batch[node];
        red_add_v4(&g_pool[g * HID + c0], acc);
    } else {
        float4 b = *reinterpret_cast<const float4*>(&bias[c0]);
        acc.x = fmaxf(acc.x + b.x, 0.f);
        acc.y = fmaxf(acc.y + b.y, 0.f);
        acc.z = fmaxf(acc.z + b.z, 0.f);
        acc.w = fmaxf(acc.w + b.w, 0.f);
        *reinterpret_cast<float4*>(&g_b[node * HID + c0]) = acc;
    }
}

// Warp per graph: out[g, c] = (pool[g]/cnt) @ M + has*bv + bout
__global__ void k_final(const float* __restrict__ bout,
                        float* __restrict__ out) {
    int gt   = blockIdx.x * blockDim.x + threadIdx.x;
    int g    = gt >> 5;
    int lane = gt & 31;
    if (g >= NGRAPH || lane >= NCLS) return;
    float cnt = (float)(g_ge[g] - g_gs[g]);
    float inv = cnt > 0.f ? 1.0f / cnt : 0.0f;
    float has = cnt > 0.f ? 1.0f : 0.0f;
    float acc = bout[lane] + has * g_bv[lane];
    #pragma unroll
    for (int h = 0; h < HID; ++h)
        acc += g_pool[g * HID + h] * inv * g_M[h * NCLS + lane];
    out[g * NCLS + lane] = acc;
}

// ---------------------------------------------------------------------------
extern "C" void kernel_launch(void* const* d_in, const int* in_sizes, int n_in,
                              void* d_out, int out_size) {
    const float* x    = (const float*)d_in[0];
    const int*   ei   = (const int*)  d_in[1];   // int32 (JAX x64 disabled)
    const int*   bat  = (const int*)  d_in[2];
    const float* W1   = (const float*)d_in[3];
    const float* b1   = (const float*)d_in[4];
    const float* W2   = (const float*)d_in[5];
    const float* b2   = (const float*)d_in[6];
    const float* Wout = (const float*)d_in[7];
    const float* bout = (const float*)d_in[8];
    float* out = (float*)d_out;

    float* pa;  cudaGetSymbolAddress((void**)&pa, g_a);

    // Side stream + fork/join events: created lazily on the FIRST call, which
    // is the uncaptured correctness run (no creation during graph capture).
    static cudaStream_t sB = nullptr;
    static cudaEvent_t evRoot = nullptr, evGemm = nullptr;
    if (sB == nullptr) {
        cudaStreamCreateWithFlags(&sB, cudaStreamNonBlocking);
        cudaEventCreateWithFlags(&evRoot, cudaEventDisableTiming);
        cudaEventCreateWithFlags(&evGemm, cudaEventDisableTiming);
    }

    const int TB = 256;
    const int initN  = (N_NODES > NGRAPH * HID) ? N_NODES : NGRAPH * HID;
    const int nblkI  = (initN + TB - 1) / TB;
    const int nblkE4 = (N_EDGES + 1023) / 1024;
    const int nblkG  = (N_NODES + 63) / 64;
    const int nblkAg = (N_NODES + 15) / 16;

    // Fork: gemm1 + head precompute on sB, concurrent with CSR build.
    cudaEventRecord(evRoot, 0);
    cudaStreamWaitEvent(sB, evRoot, 0);
    k_gemm<F_INDIM><<<nblkG, TB, 0, sB>>>(x, W1, pa);
    k_prep<<<1, TB, 0, sB>>>(W2, b2, Wout);
    cudaEventRecord(evGemm, sB);

    // CSR build on the main (capture) stream.
    k_init   <<<nblkI, TB>>>();
    k_count  <<<nblkE4, TB>>>(ei);
    k_scan1  <<<NSBLK, SBLK>>>();
    k_scan2  <<<1, SBLK>>>();
    k_scan3  <<<NSBLK, SBLK>>>(bat);     // + graph segment boundaries
    k_scatter<<<nblkE4, TB>>>(ei);

    // Join: agg1 needs gemm1 output and the CSR. Epilogue applies relu(+b1).
    cudaStreamWaitEvent(0, evGemm, 0);
    k_agg_csr<false><<<nblkAg, TB>>>(bat, b1);

    // Layer-2 aggregation fused with mean pooling (gemm2 folded into head).
    k_agg_csr<true><<<nblkAg, TB>>>(bat, nullptr);

    // Head: out = (pool/cnt) @ M + has*(b2 Wout) + bout
    k_final<<<(NGRAPH * 32 + TB - 1) / TB, TB>>>(bout, out);
}

// round 15
// speedup vs baseline: 1.7884x; 1.1464x over previous
#include <cuda_runtime.h>
#include <cuda_bf16.h>
#include <cstdint>

#define N_NODES 50000
#define N_EDGES 1600000
#define F_INDIM 128
#define HID     64
#define NCLS    19
#define NGRAPH  512
#define SBLK    256
#define NSBLK   ((N_NODES + SBLK - 1) / SBLK)   // 196

// ---- scratch (static device globals; no allocation) ----
__device__ int   g_ecnt[N_NODES];
__device__ int   g_off [N_NODES + 1];
__device__ int   g_cur [N_NODES];
__device__ int   g_part[NSBLK];
__device__ int2  g_edge[N_EDGES];         // packed (src, __float_as_int(norm))
__device__ float g_dinv[N_NODES];
__device__ uint2 g_ah  [N_NODES * 16];    // bf16 rows: 16 x uint2 = 64 feats
__device__ uint2 g_bh  [N_NODES * 16];    // h1 in bf16
__device__ float g_pool[NGRAPH * HID];
__device__ int   g_gs  [NGRAPH];          // first node index of graph (sorted batch)
__device__ int   g_ge  [NGRAPH];          // one past last node index
__device__ float g_M   [HID * NCLS];      // W2 @ Wout
__device__ float g_bv  [NCLS];            // b2 @ Wout

__device__ __forceinline__ void red_add_v4(float* addr, float4 v) {
    asm volatile("red.global.add.v4.f32 [%0], {%1, %2, %3, %4};"
                 :: "l"(addr), "f"(v.x), "f"(v.y), "f"(v.z), "f"(v.w)
                 : "memory");
}

__device__ __forceinline__ float2 bf2_to_f2(uint32_t u) {
    __nv_bfloat162 h = *reinterpret_cast<__nv_bfloat162*>(&u);
    return __bfloat1622float2(h);
}
__device__ __forceinline__ uint32_t f2_to_bf2(float a, float b) {
    __nv_bfloat162 h = __float22bfloat162_rn(make_float2(a, b));
    return *reinterpret_cast<uint32_t*>(&h);
}

// ---------------------------------------------------------------------------
__global__ void k_init() {
    int i = blockIdx.x * blockDim.x + threadIdx.x;
    if (i < N_NODES)       g_ecnt[i] = 0;
    if (i < NGRAPH * HID)  g_pool[i] = 0.f;
    if (i < NGRAPH)        { g_gs[i] = 0; g_ge[i] = 0; }
}

// 4 consecutive-stride edges per thread.
__global__ void k_count(const int* __restrict__ ei) {
    const int base = blockIdx.x * 1024 + threadIdx.x;
    #pragma unroll
    for (int j = 0; j < 4; ++j) {
        int e = base + j * 256;
        if (e < N_EDGES) atomicAdd(&g_ecnt[ei[N_EDGES + e]], 1);
    }
}

// ---- scan phase 1 (+dinv) --------------------------------------------------
__global__ void k_scan1() {
    __shared__ int sh[SBLK];
    const int t = threadIdx.x;
    const int i = blockIdx.x * SBLK + t;
    int v = (i < N_NODES) ? g_ecnt[i] : 0;
    if (i < N_NODES) g_dinv[i] = rsqrtf(1.0f + (float)v);   // +1 self-loop
    sh[t] = v;
    __syncthreads();
    #pragma unroll
    for (int off = 1; off < SBLK; off <<= 1) {
        int u = (t >= off) ? sh[t - off] : 0;
        __syncthreads();
        if (t >= off) sh[t] += u;
        __syncthreads();
    }
    if (i < N_NODES) g_off[i] = sh[t] - v;
    if (t == SBLK - 1) g_part[blockIdx.x] = sh[t];
}

__global__ void k_scan2() {
    __shared__ int sh[SBLK];
    const int t = threadIdx.x;
    int v = (t < NSBLK) ? g_part[t] : 0;
    sh[t] = v;
    __syncthreads();
    #pragma unroll
    for (int off = 1; off < SBLK; off <<= 1) {
        int u = (t >= off) ? sh[t - off] : 0;
        __syncthreads();
        if (t >= off) sh[t] += u;
        __syncthreads();
    }
    if (t < NSBLK) g_part[t] = sh[t] - v;
    if (t == SBLK - 1) g_off[N_NODES] = sh[t];
}

// Phase 3 + graph segment boundaries (batch is sorted; no atomics).
__global__ void k_scan3(const int* __restrict__ batch) {
    const int i = blockIdx.x * SBLK + threadIdx.x;
    if (i < N_NODES) {
        int o = g_off[i] + g_part[blockIdx.x];
        g_off[i] = o;
        g_cur[i] = o;
        int b  = batch[i];
        int bl = (i > 0)           ? batch[i - 1] : -1;
        int br = (i < N_NODES - 1) ? batch[i + 1] : -1;
        if (b != bl) g_gs[b] = i;
        if (b != br) g_ge[b] = i + 1;
    }
}

// 4 edges per thread.
__global__ void k_scatter(const int* __restrict__ ei) {
    const int base = blockIdx.x * 1024 + threadIdx.x;
    #pragma unroll
    for (int j = 0; j < 4; ++j) {
        int e = base + j * 256;
        if (e < N_EDGES) {
            int s = ei[e];
            int d = ei[N_EDGES + e];
            int pos = atomicAdd(&g_cur[d], 1);
            g_edge[pos] = make_int2(s, __float_as_int(g_dinv[s] * g_dinv[d]));
        }
    }
}

// ---------------------------------------------------------------------------
// Tiny precompute: M = W2 @ Wout [64,19], bv = b2 @ Wout [19]. One block.
__global__ void k_prep(const float* __restrict__ W2, const float* __restrict__ b2,
                       const float* __restrict__ Wout) {
    int idx = threadIdx.x;                              // 256 threads
    for (int i = idx; i < HID * NCLS; i += 256) {
        int k = i / NCLS, c = i % NCLS;
        float s = 0.f;
        #pragma unroll
        for (int h = 0; h < HID; ++h) s += W2[k * HID + h] * Wout[h * NCLS + c];
        g_M[i] = s;
    }
    if (idx < NCLS) {
        float s = 0.f;
        #pragma unroll
        for (int h = 0; h < HID; ++h) s += b2[h] * Wout[h * NCLS + idx];
        g_bv[idx] = s;
    }
}

// ---------------------------------------------------------------------------
// Register-tiled GEMM (protected R7 shape); epilogue stores bf16 rows.
template <int K>
__global__ void k_gemm(const float* __restrict__ X, const float* __restrict__ W) {
    constexpr int XP = K + 4;
    __shared__ float Xs[64 * XP];
    __shared__ float Ws[K * HID];
    const int tid = threadIdx.x;
    const int nb  = blockIdx.x * 64;

    for (int i = tid; i < K * HID; i += 256) Ws[i] = W[i];
    for (int i = tid; i < 64 * K; i += 256) {
        int nl = i / K, k = i % K;
        int node = nb + nl;
        Xs[nl * XP + k] = (node < N_NODES) ? X[node * K + k] : 0.0f;
    }
    __syncthreads();

    const int ny0 = (tid / 16) * 4;
    const int c0  = (tid & 15) * 4;

    float4 acc[4];
    #pragma unroll
    for (int i = 0; i < 4; ++i) acc[i] = make_float4(0.f, 0.f, 0.f, 0.f);

    #pragma unroll 4
    for (int k = 0; k < K; k += 4) {
        float4 xr[4], wr[4];
        #pragma unroll
        for (int i = 0; i < 4; ++i)
            xr[i] = *reinterpret_cast<const float4*>(&Xs[(ny0 + i) * XP + k]);
        #pragma unroll
        for (int j = 0; j < 4; ++j)
            wr[j] = *reinterpret_cast<const float4*>(&Ws[(k + j) * HID + c0]);
        #pragma unroll
        for (int i = 0; i < 4; ++i) {
            const float x0 = xr[i].x, x1 = xr[i].y, x2 = xr[i].z, x3 = xr[i].w;
            acc[i].x += x0*wr[0].x + x1*wr[1].x + x2*wr[2].x + x3*wr[3].x;
            acc[i].y += x0*wr[0].y + x1*wr[1].y + x2*wr[2].y + x3*wr[3].y;
            acc[i].z += x0*wr[0].z + x1*wr[1].z + x2*wr[2].z + x3*wr[3].z;
            acc[i].w += x0*wr[0].w + x1*wr[1].w + x2*wr[2].w + x3*wr[3].w;
        }
    }

    #pragma unroll
    for (int i = 0; i < 4; ++i) {
        int node = nb + ny0 + i;
        if (node >= N_NODES) break;
        g_ah[node * 16 + (tid & 15)] =
            make_uint2(f2_to_bf2(acc[i].x, acc[i].y), f2_to_bf2(acc[i].z, acc[i].w));
    }
}

// ---------------------------------------------------------------------------
// CSR aggregation over bf16 rows. 16 lanes per node (same geometry as fp32
// version); lane owns 4 features = one uint2 (8 B) gather per edge.
// fp32 accumulate. Layer 1: epilogue relu(+b1) -> bf16 g_bh.
// Layer 2: red.v4 into fp32 g_pool.
template <bool POOL>
__global__ void k_agg_csr(const int* __restrict__ batch,
                          const float* __restrict__ bias) {
    const int node = blockIdx.x * 16 + (threadIdx.x >> 4);
    const int l    = threadIdx.x & 15;
    if (node >= N_NODES) return;

    const uint2* __restrict__ src = POOL ? g_bh : g_ah;

    float dn = g_dinv[node]; dn *= dn;
    uint2 rs = src[node * 16 + l];
    float2 s0 = bf2_to_f2(rs.x), s1 = bf2_to_f2(rs.y);
    float a0 = dn * s0.x, a1 = dn * s0.y, a2 = dn * s1.x, a3 = dn * s1.y;

    const int beg = g_off[node];
    const int end = g_off[node + 1];
    int e = beg;
    for (; e + 4 <= end; e += 4) {
        int2 e0 = g_edge[e],     e1 = g_edge[e + 1];
        int2 e2 = g_edge[e + 2], e3 = g_edge[e + 3];
        uint2 r0 = src[e0.x * 16 + l];
        uint2 r1 = src[e1.x * 16 + l];
        uint2 r2 = src[e2.x * 16 + l];
        uint2 r3 = src[e3.x * 16 + l];
        float n0 = __int_as_float(e0.y), n1 = __int_as_float(e1.y);
        float n2 = __int_as_float(e2.y), n3 = __int_as_float(e3.y);
        float2 f;
        f = bf2_to_f2(r0.x); a0 += n0*f.x; a1 += n0*f.y;
        f = bf2_to_f2(r0.y); a2 += n0*f.x; a3 += n0*f.y;
        f = bf2_to_f2(r1.x); a0 += n1*f.x; a1 += n1*f.y;
        f = bf2_to_f2(r1.y); a2 += n1*f.x; a3 += n1*f.y;
        f = bf2_to_f2(r2.x); a0 += n2*f.x; a1 += n2*f.y;
        f = bf2_to_f2(r2.y); a2 += n2*f.x; a3 += n2*f.y;
        f = bf2_to_f2(r3.x); a0 += n3*f.x; a1 += n3*f.y;
        f = bf2_to_f2(r3.y); a2 += n3*f.x; a3 += n3*f.y;
    }
    for (; e < end; ++e) {
        int2 e0 = g_edge[e];
        float n0 = __int_as_float(e0.y);
        uint2 r0 = src[e0.x * 16 + l];
        float2 f;
        f = bf2_to_f2(r0.x); a0 += n0*f.x; a1 += n0*f.y;
        f = bf2_to_f2(r0.y); a2 += n0*f.x; a3 += n0*f.y;
    }

    if (POOL) {
        int g = batch[node];
        red_add_v4(&g_pool[g * HID + l * 4], make_float4(a0, a1, a2, a3));
    } else {
        float4 b = *reinterpret_cast<const float4*>(&bias[l * 4]);
        a0 = fmaxf(a0 + b.x, 0.f);
        a1 = fmaxf(a1 + b.y, 0.f);
        a2 = fmaxf(a2 + b.z, 0.f);
        a3 = fmaxf(a3 + b.w, 0.f);
        g_bh[node * 16 + l] = make_uint2(f2_to_bf2(a0, a1), f2_to_bf2(a2, a3));
    }
}

// Warp per graph: out[g, c] = (pool[g]/cnt) @ M + has*bv + bout
__global__ void k_final(const float* __restrict__ bout,
                        float* __restrict__ out) {
    int gt   = blockIdx.x * blockDim.x + threadIdx.x;
    int g    = gt >> 5;
    int lane = gt & 31;
    if (g >= NGRAPH || lane >= NCLS) return;
    float cnt = (float)(g_ge[g] - g_gs[g]);
    float inv = cnt > 0.f ? 1.0f / cnt : 0.0f;
    float has = cnt > 0.f ? 1.0f : 0.0f;
    float acc = bout[lane] + has * g_bv[lane];
    #pragma unroll
    for (int h = 0; h < HID; ++h)
        acc += g_pool[g * HID + h] * inv * g_M[h * NCLS + lane];
    out[g * NCLS + lane] = acc;
}

// ---------------------------------------------------------------------------
extern "C" void kernel_launch(void* const* d_in, const int* in_sizes, int n_in,
                              void* d_out, int out_size) {
    const float* x    = (const float*)d_in[0];
    const int*   ei   = (const int*)  d_in[1];   // int32 (JAX x64 disabled)
    const int*   bat  = (const int*)  d_in[2];
    const float* W1   = (const float*)d_in[3];
    const float* b1   = (const float*)d_in[4];
    const float* W2   = (const float*)d_in[5];
    const float* b2   = (const float*)d_in[6];
    const float* Wout = (const float*)d_in[7];
    const float* bout = (const float*)d_in[8];
    float* out = (float*)d_out;

    // Side stream + fork/join events: created lazily on the FIRST call, which
    // is the uncaptured correctness run (no creation during graph capture).
    static cudaStream_t sB = nullptr;
    static cudaEvent_t evRoot = nullptr, evGemm = nullptr;
    if (sB == nullptr) {
        cudaStreamCreateWithFlags(&sB, cudaStreamNonBlocking);
        cudaEventCreateWithFlags(&evRoot, cudaEventDisableTiming);
        cudaEventCreateWithFlags(&evGemm, cudaEventDisableTiming);
    }

    const int TB = 256;
    const int initN  = (N_NODES > NGRAPH * HID) ? N_NODES : NGRAPH * HID;
    const int nblkI  = (initN + TB - 1) / TB;
    const int nblkE4 = (N_EDGES + 1023) / 1024;
    const int nblkG  = (N_NODES + 63) / 64;
    const int nblkAg = (N_NODES + 15) / 16;

    // Fork: gemm1 + head precompute on sB, concurrent with CSR build.
    cudaEventRecord(evRoot, 0);
    cudaStreamWaitEvent(sB, evRoot, 0);
    k_gemm<F_INDIM><<<nblkG, TB, 0, sB>>>(x, W1);
    k_prep<<<1, TB, 0, sB>>>(W2, b2, Wout);
    cudaEventRecord(evGemm, sB);

    // CSR build on the main (capture) stream.
    k_init   <<<nblkI, TB>>>();
    k_count  <<<nblkE4, TB>>>(ei);
    k_scan1  <<<NSBLK, SBLK>>>();
    k_scan2  <<<1, SBLK>>>();
    k_scan3  <<<NSBLK, SBLK>>>(bat);     // + graph segment boundaries
    k_scatter<<<nblkE4, TB>>>(ei);

    // Join: agg1 needs gemm1 output and the CSR. Epilogue applies relu(+b1).
    cudaStreamWaitEvent(0, evGemm, 0);
    k_agg_csr<false><<<nblkAg, TB>>>(bat, b1);

    // Layer-2 aggregation fused with mean pooling (gemm2 folded into head).
    k_agg_csr<true><<<nblkAg, TB>>>(bat, nullptr);

    // Head: out = (pool/cnt) @ M + has*(b2 Wout) + bout
    k_final<<<(NGRAPH * 32 + TB - 1) / TB, TB>>>(bout, out);
}

// round 16
// speedup vs baseline: 1.8300x; 1.0232x over previous
#include <cuda_runtime.h>
#include <cuda_bf16.h>
#include <cstdint>

#define N_NODES 50000
#define N_EDGES 1600000
#define F_INDIM 128
#define HID     64
#define NCLS    19
#define NGRAPH  512
#define SBLK    256
#define NSBLK   ((N_NODES + SBLK - 1) / SBLK)   // 196

// ---- scratch (static device globals; no allocation) ----
__device__ int   g_ecnt4[4][N_NODES];     // 4-way split histograms (class = e & 3)
__device__ int   g_off [N_NODES + 1];
__device__ int   g_cur4[4][N_NODES];      // per-class scatter cursors
__device__ int   g_part[NSBLK];
__device__ int2  g_edge[N_EDGES];         // packed (src, __float_as_int(norm))
__device__ float g_dinv[N_NODES];
__device__ uint2 g_ah  [N_NODES * 16];    // bf16 rows: 16 x uint2 = 64 feats
__device__ uint2 g_bh  [N_NODES * 16];    // h1 in bf16
__device__ float g_pool[NGRAPH * HID];
__device__ int   g_gs  [NGRAPH];          // first node index of graph (sorted batch)
__device__ int   g_ge  [NGRAPH];          // one past last node index
__device__ float g_M   [HID * NCLS];      // W2 @ Wout
__device__ float g_bv  [NCLS];            // b2 @ Wout

__device__ __forceinline__ void red_add_v4(float* addr, float4 v) {
    asm volatile("red.global.add.v4.f32 [%0], {%1, %2, %3, %4};"
                 :: "l"(addr), "f"(v.x), "f"(v.y), "f"(v.z), "f"(v.w)
                 : "memory");
}

__device__ __forceinline__ float2 bf2_to_f2(uint32_t u) {
    __nv_bfloat162 h = *reinterpret_cast<__nv_bfloat162*>(&u);
    return __bfloat1622float2(h);
}
__device__ __forceinline__ uint32_t f2_to_bf2(float a, float b) {
    __nv_bfloat162 h = __float22bfloat162_rn(make_float2(a, b));
    return *reinterpret_cast<uint32_t*>(&h);
}

// ---------------------------------------------------------------------------
// Zero 4 histograms (flat 4*N), pool, segment bounds. Grid covers 4*N_NODES.
__global__ void k_init() {
    int i = blockIdx.x * blockDim.x + threadIdx.x;
    if (i < 4 * N_NODES)   (&g_ecnt4[0][0])[i] = 0;
    if (i < NGRAPH * HID)  g_pool[i] = 0.f;
    if (i < NGRAPH)        { g_gs[i] = 0; g_ge[i] = 0; }
}

// 4 edges per thread; class = e & 3 selects histogram copy (collisions /4).
__global__ void k_count(const int* __restrict__ ei) {
    const int base = blockIdx.x * 1024 + threadIdx.x;
    #pragma unroll
    for (int j = 0; j < 4; ++j) {
        int e = base + j * 256;
        if (e < N_EDGES) atomicAdd(&g_ecnt4[e & 3][ei[N_EDGES + e]], 1);
    }
}

// ---- scan phase 1 (+dinv): v = sum of 4 class counts ----------------------
__global__ void k_scan1() {
    __shared__ int sh[SBLK];
    const int t = threadIdx.x;
    const int i = blockIdx.x * SBLK + t;
    int v = 0;
    if (i < N_NODES) {
        v = g_ecnt4[0][i] + g_ecnt4[1][i] + g_ecnt4[2][i] + g_ecnt4[3][i];
        g_dinv[i] = rsqrtf(1.0f + (float)v);   // +1 self-loop
    }
    sh[t] = v;
    __syncthreads();
    #pragma unroll
    for (int off = 1; off < SBLK; off <<= 1) {
        int u = (t >= off) ? sh[t - off] : 0;
        __syncthreads();
        if (t >= off) sh[t] += u;
        __syncthreads();
    }
    if (i < N_NODES) g_off[i] = sh[t] - v;
    if (t == SBLK - 1) g_part[blockIdx.x] = sh[t];
}

__global__ void k_scan2() {
    __shared__ int sh[SBLK];
    const int t = threadIdx.x;
    int v = (t < NSBLK) ? g_part[t] : 0;
    sh[t] = v;
    __syncthreads();
    #pragma unroll
    for (int off = 1; off < SBLK; off <<= 1) {
        int u = (t >= off) ? sh[t - off] : 0;
        __syncthreads();
        if (t >= off) sh[t] += u;
        __syncthreads();
    }
    if (t < NSBLK) g_part[t] = sh[t] - v;
    if (t == SBLK - 1) g_off[N_NODES] = sh[t];
}

// Phase 3: finalize offsets, derive 4 per-class cursors, graph segments.
__global__ void k_scan3(const int* __restrict__ batch) {
    const int i = blockIdx.x * SBLK + threadIdx.x;
    if (i < N_NODES) {
        int o = g_off[i] + g_part[blockIdx.x];
        g_off[i] = o;
        int c0 = g_ecnt4[0][i], c1 = g_ecnt4[1][i], c2 = g_ecnt4[2][i];
        g_cur4[0][i] = o;
        g_cur4[1][i] = o + c0;
        g_cur4[2][i] = o + c0 + c1;
        g_cur4[3][i] = o + c0 + c1 + c2;
        int b  = batch[i];
        int bl = (i > 0)           ? batch[i - 1] : -1;
        int br = (i < N_NODES - 1) ? batch[i + 1] : -1;
        if (b != bl) g_gs[b] = i;
        if (b != br) g_ge[b] = i + 1;
    }
}

// 4 edges per thread; per-class cursor (collisions /4).
__global__ void k_scatter(const int* __restrict__ ei) {
    const int base = blockIdx.x * 1024 + threadIdx.x;
    #pragma unroll
    for (int j = 0; j < 4; ++j) {
        int e = base + j * 256;
        if (e < N_EDGES) {
            int s = ei[e];
            int d = ei[N_EDGES + e];
            int pos = atomicAdd(&g_cur4[e & 3][d], 1);
            g_edge[pos] = make_int2(s, __float_as_int(g_dinv[s] * g_dinv[d]));
        }
    }
}

// ---------------------------------------------------------------------------
// Tiny precompute: M = W2 @ Wout [64,19], bv = b2 @ Wout [19]. One block.
__global__ void k_prep(const float* __restrict__ W2, const float* __restrict__ b2,
                       const float* __restrict__ Wout) {
    int idx = threadIdx.x;                              // 256 threads
    for (int i = idx; i < HID * NCLS; i += 256) {
        int k = i / NCLS, c = i % NCLS;
        float s = 0.f;
        #pragma unroll
        for (int h = 0; h < HID; ++h) s += W2[k * HID + h] * Wout[h * NCLS + c];
        g_M[i] = s;
    }
    if (idx < NCLS) {
        float s = 0.f;
        #pragma unroll
        for (int h = 0; h < HID; ++h) s += b2[h] * Wout[h * NCLS + idx];
        g_bv[idx] = s;
    }
}

// ---------------------------------------------------------------------------
// Register-tiled GEMM (protected R7 shape); epilogue stores bf16 rows.
template <int K>
__global__ void k_gemm(const float* __restrict__ X, const float* __restrict__ W) {
    constexpr int XP = K + 4;
    __shared__ float Xs[64 * XP];
    __shared__ float Ws[K * HID];
    const int tid = threadIdx.x;
    const int nb  = blockIdx.x * 64;

    for (int i = tid; i < K * HID; i += 256) Ws[i] = W[i];
    for (int i = tid; i < 64 * K; i += 256) {
        int nl = i / K, k = i % K;
        int node = nb + nl;
        Xs[nl * XP + k] = (node < N_NODES) ? X[node * K + k] : 0.0f;
    }
    __syncthreads();

    const int ny0 = (tid / 16) * 4;
    const int c0  = (tid & 15) * 4;

    float4 acc[4];
    #pragma unroll
    for (int i = 0; i < 4; ++i) acc[i] = make_float4(0.f, 0.f, 0.f, 0.f);

    #pragma unroll 4
    for (int k = 0; k < K; k += 4) {
        float4 xr[4], wr[4];
        #pragma unroll
        for (int i = 0; i < 4; ++i)
            xr[i] = *reinterpret_cast<const float4*>(&Xs[(ny0 + i) * XP + k]);
        #pragma unroll
        for (int j = 0; j < 4; ++j)
            wr[j] = *reinterpret_cast<const float4*>(&Ws[(k + j) * HID + c0]);
        #pragma unroll
        for (int i = 0; i < 4; ++i) {
            const float x0 = xr[i].x, x1 = xr[i].y, x2 = xr[i].z, x3 = xr[i].w;
            acc[i].x += x0*wr[0].x + x1*wr[1].x + x2*wr[2].x + x3*wr[3].x;
            acc[i].y += x0*wr[0].y + x1*wr[1].y + x2*wr[2].y + x3*wr[3].y;
            acc[i].z += x0*wr[0].z + x1*wr[1].z + x2*wr[2].z + x3*wr[3].z;
            acc[i].w += x0*wr[0].w + x1*wr[1].w + x2*wr[2].w + x3*wr[3].w;
        }
    }

    #pragma unroll
    for (int i = 0; i < 4; ++i) {
        int node = nb + ny0 + i;
        if (node >= N_NODES) break;
        g_ah[node * 16 + (tid & 15)] =
            make_uint2(f2_to_bf2(acc[i].x, acc[i].y), f2_to_bf2(acc[i].z, acc[i].w));
    }
}

// ---------------------------------------------------------------------------
// CSR aggregation over bf16 rows. 16 lanes per node; lane owns 4 features
// = one uint2 (8 B) gather per edge. fp32 accumulate.
template <bool POOL>
__global__ void k_agg_csr(const int* __restrict__ batch,
                          const float* __restrict__ bias) {
    const int node = blockIdx.x * 16 + (threadIdx.x >> 4);
    const int l    = threadIdx.x & 15;
    if (node >= N_NODES) return;

    const uint2* __restrict__ src = POOL ? g_bh : g_ah;

    float dn = g_dinv[node]; dn *= dn;
    uint2 rs = src[node * 16 + l];
    float2 s0 = bf2_to_f2(rs.x), s1 = bf2_to_f2(rs.y);
    float a0 = dn * s0.x, a1 = dn * s0.y, a2 = dn * s1.x, a3 = dn * s1.y;

    const int beg = g_off[node];
    const int end = g_off[node + 1];
    int e = beg;
    for (; e + 4 <= end; e += 4) {
        int2 e0 = g_edge[e],     e1 = g_edge[e + 1];
        int2 e2 = g_edge[e + 2], e3 = g_edge[e + 3];
        uint2 r0 = src[e0.x * 16 + l];
        uint2 r1 = src[e1.x * 16 + l];
        uint2 r2 = src[e2.x * 16 + l];
        uint2 r3 = src[e3.x * 16 + l];
        float n0 = __int_as_float(e0.y), n1 = __int_as_float(e1.y);
        float n2 = __int_as_float(e2.y), n3 = __int_as_float(e3.y);
        float2 f;
        f = bf2_to_f2(r0.x); a0 += n0*f.x; a1 += n0*f.y;
        f = bf2_to_f2(r0.y); a2 += n0*f.x; a3 += n0*f.y;
        f = bf2_to_f2(r1.x); a0 += n1*f.x; a1 += n1*f.y;
        f = bf2_to_f2(r1.y); a2 += n1*f.x; a3 += n1*f.y;
        f = bf2_to_f2(r2.x); a0 += n2*f.x; a1 += n2*f.y;
        f = bf2_to_f2(r2.y); a2 += n2*f.x; a3 += n2*f.y;
        f = bf2_to_f2(r3.x); a0 += n3*f.x; a1 += n3*f.y;
        f = bf2_to_f2(r3.y); a2 += n3*f.x; a3 += n3*f.y;
    }
    for (; e < end; ++e) {
        int2 e0 = g_edge[e];
        float n0 = __int_as_float(e0.y);
        uint2 r0 = src[e0.x * 16 + l];
        float2 f;
        f = bf2_to_f2(r0.x); a0 += n0*f.x; a1 += n0*f.y;
        f = bf2_to_f2(r0.y); a2 += n0*f.x; a3 += n0*f.y;
    }

    if (POOL) {
        int g = batch[node];
        red_add_v4(&g_pool[g * HID + l * 4], make_float4(a0, a1, a2, a3));
    } else {
        float4 b = *reinterpret_cast<const float4*>(&bias[l * 4]);
        a0 = fmaxf(a0 + b.x, 0.f);
        a1 = fmaxf(a1 + b.y, 0.f);
        a2 = fmaxf(a2 + b.z, 0.f);
        a3 = fmaxf(a3 + b.w, 0.f);
        g_bh[node * 16 + l] = make_uint2(f2_to_bf2(a0, a1), f2_to_bf2(a2, a3));
    }
}

// Warp per graph: out[g, c] = (pool[g]/cnt) @ M + has*bv + bout
__global__ void k_final(const float* __restrict__ bout,
                        float* __restrict__ out) {
    int gt   = blockIdx.x * blockDim.x + threadIdx.x;
    int g    = gt >> 5;
    int lane = gt & 31;
    if (g >= NGRAPH || lane >= NCLS) return;
    float cnt = (float)(g_ge[g] - g_gs[g]);
    float inv = cnt > 0.f ? 1.0f / cnt : 0.0f;
    float has = cnt > 0.f ? 1.0f : 0.0f;
    float acc = bout[lane] + has * g_bv[lane];
    #pragma unroll
    for (int h = 0; h < HID; ++h)
        acc += g_pool[g * HID + h] * inv * g_M[h * NCLS + lane];
    out[g * NCLS + lane] = acc;
}

// ---------------------------------------------------------------------------
extern "C" void kernel_launch(void* const* d_in, const int* in_sizes, int n_in,
                              void* d_out, int out_size) {
    const float* x    = (const float*)d_in[0];
    const int*   ei   = (const int*)  d_in[1];   // int32 (JAX x64 disabled)
    const int*   bat  = (const int*)  d_in[2];
    const float* W1   = (const float*)d_in[3];
    const float* b1   = (const float*)d_in[4];
    const float* W2   = (const float*)d_in[5];
    const float* b2   = (const float*)d_in[6];
    const float* Wout = (const float*)d_in[7];
    const float* bout = (const float*)d_in[8];
    float* out = (float*)d_out;

    // Side stream + fork/join events: created lazily on the FIRST call, which
    // is the uncaptured correctness run (no creation during graph capture).
    static cudaStream_t sB = nullptr;
    static cudaEvent_t evRoot = nullptr, evGemm = nullptr;
    if (sB == nullptr) {
        cudaStreamCreateWithFlags(&sB, cudaStreamNonBlocking);
        cudaEventCreateWithFlags(&evRoot, cudaEventDisableTiming);
        cudaEventCreateWithFlags(&evGemm, cudaEventDisableTiming);
    }

    const int TB = 256;
    const int nblkI  = (4 * N_NODES + TB - 1) / TB;   // covers all histograms
    const int nblkE4 = (N_EDGES + 1023) / 1024;
    const int nblkG  = (N_NODES + 63) / 64;
    const int nblkAg = (N_NODES + 15) / 16;

    // Fork: gemm1 + head precompute on sB, concurrent with CSR build.
    cudaEventRecord(evRoot, 0);
    cudaStreamWaitEvent(sB, evRoot, 0);
    k_gemm<F_INDIM><<<nblkG, TB, 0, sB>>>(x, W1);
    k_prep<<<1, TB, 0, sB>>>(W2, b2, Wout);
    cudaEventRecord(evGemm, sB);

    // CSR build on the main (capture) stream.
    k_init   <<<nblkI, TB>>>();
    k_count  <<<nblkE4, TB>>>(ei);
    k_scan1  <<<NSBLK, SBLK>>>();
    k_scan2  <<<1, SBLK>>>();
    k_scan3  <<<NSBLK, SBLK>>>(bat);     // + per-class cursors + segments
    k_scatter<<<nblkE4, TB>>>(ei);

    // Join: agg1 needs gemm1 output and the CSR. Epilogue applies relu(+b1).
    cudaStreamWaitEvent(0, evGemm, 0);
    k_agg_csr<false><<<nblkAg, TB>>>(bat, b1);

    // Layer-2 aggregation fused with mean pooling (gemm2 folded into head).
    k_agg_csr<true><<<nblkAg, TB>>>(bat, nullptr);

    // Head: out = (pool/cnt) @ M + has*(b2 Wout) + bout
    k_final<<<(NGRAPH * 32 + TB - 1) / TB, TB>>>(bout, out);
}